// round 2
// baseline (speedup 1.0000x reference)
#include <cuda_runtime.h>

#define NN 50000
#define NE 800000
#define D  64
#define NL 3
#define DCAT (D + NL * D)   // 256

// ---------------- scratch (device globals; no allocation allowed) ----------
__device__ int   g_cnt1[NN], g_cnt2[NN], g_cur1[NN], g_cur2[NN];
__device__ int   g_off1[NN + 1], g_off2[NN + 1];
__device__ int   g_nbr1[NE], g_nbr2[NE];
__device__ float g_h[NN * D];
__device__ float g_m1[NN * D], g_m2[NN * D], g_r[NN * D];
__device__ float g_cat[NN * DCAT];

__device__ __forceinline__ int clampi(int v) {
    return v < 0 ? 0 : (v >= NN ? NN - 1 : v);
}

// ---------------- init: h = x, cat[:, :64] = x, zero CSR counters ----------
__global__ void k_init(const float* __restrict__ x) {
    int i = blockIdx.x * blockDim.x + threadIdx.x;
    if (i < NN * D) {
        float v = x[i];
        g_h[i] = v;
        g_cat[(i >> 6) * DCAT + (i & 63)] = v;
    }
    if (i < NN) {
        g_cnt1[i] = 0; g_cnt2[i] = 0;
        g_cur1[i] = 0; g_cur2[i] = 0;
    }
}

// ---------------- CSR build: histogram -------------------------------------
// edge_index is int32 (JAX without x64 silently downcasts int64 -> int32).
__global__ void k_count(const int* __restrict__ ei) {
    int e = blockIdx.x * blockDim.x + threadIdx.x;
    if (e >= NE) return;
    int s = clampi(ei[e]);
    int d = clampi(ei[NE + e]);
    atomicAdd(&g_cnt1[d], 1);   // CSR1: grouped by dst, stores src (for out1)
    atomicAdd(&g_cnt2[s], 1);   // CSR2: grouped by src, stores dst (for out2)
}

// ---------------- CSR build: single-block exclusive scan -------------------
__global__ void k_scan() {
    __shared__ int ssum1[1024], ssum2[1024];
    const int t  = threadIdx.x;
    const int CH = (NN + 1023) / 1024;  // 49
    const int base = t * CH;

    int s1 = 0, s2 = 0;
    for (int i = 0; i < CH; i++) {
        int n = base + i;
        if (n < NN) { s1 += g_cnt1[n]; s2 += g_cnt2[n]; }
    }
    ssum1[t] = s1; ssum2[t] = s2;
    __syncthreads();

    // Hillis-Steele inclusive scan over 1024 chunk sums
    for (int off = 1; off < 1024; off <<= 1) {
        int a1 = ssum1[t], a2 = ssum2[t];
        int b1 = (t >= off) ? ssum1[t - off] : 0;
        int b2 = (t >= off) ? ssum2[t - off] : 0;
        __syncthreads();
        ssum1[t] = a1 + b1; ssum2[t] = a2 + b2;
        __syncthreads();
    }

    int ex1 = (t == 0) ? 0 : ssum1[t - 1];
    int ex2 = (t == 0) ? 0 : ssum2[t - 1];
    for (int i = 0; i < CH; i++) {
        int n = base + i;
        if (n < NN) {
            g_off1[n] = ex1; ex1 += g_cnt1[n];
            g_off2[n] = ex2; ex2 += g_cnt2[n];
        }
    }
    if (t == 0) {
        g_off1[NN] = ssum1[1023];
        g_off2[NN] = ssum2[1023];
    }
}

// ---------------- CSR build: fill edge lists --------------------------------
__global__ void k_fill(const int* __restrict__ ei) {
    int e = blockIdx.x * blockDim.x + threadIdx.x;
    if (e >= NE) return;
    int s = clampi(ei[e]);
    int d = clampi(ei[NE + e]);
    int p1 = g_off1[d] + atomicAdd(&g_cur1[d], 1);
    g_nbr1[p1] = s;
    int p2 = g_off2[s] + atomicAdd(&g_cur2[s], 1);
    g_nbr2[p2] = d;
}

// ---------------- fused projection: m1 = h@W1^T, m2 = h@W2^T, r = h@Wr^T + b
__global__ void k_proj(const float* __restrict__ w1, const float* __restrict__ w2,
                       const float* __restrict__ wr, const float* __restrict__ rb) {
    __shared__ float s1[D * D], s2[D * D], sr[D * D];   // transposed [k][c]
    const int tid = threadIdx.x;
    for (int i = tid; i < D * D; i += 256) {
        int c = i >> 6, k = i & 63;
        s1[k * D + c] = w1[i];
        s2[k * D + c] = w2[i];
        sr[k * D + c] = wr[i];
    }
    __syncthreads();

    int gid = blockIdx.x * 256 + tid;        // grid sized exactly NN*D
    int n = gid >> 6, c = gid & 63;
    float a1 = 0.f, a2 = 0.f, ar = rb[c];
    const float* __restrict__ hrow = g_h + n * D;
#pragma unroll 8
    for (int k = 0; k < D; k++) {
        float hv = hrow[k];                  // warp-uniform -> L1 broadcast
        a1 = fmaf(hv, s1[k * D + c], a1);
        a2 = fmaf(hv, s2[k * D + c], a2);
        ar = fmaf(hv, sr[k * D + c], ar);
    }
    g_m1[gid] = a1;
    g_m2[gid] = a2;
    g_r[gid]  = ar;
}

// ---------------- fused aggregation: mean(dir1) + mean(dir2) + root + ReLU --
__global__ void k_agg(int l) {
    int gw   = (blockIdx.x * blockDim.x + threadIdx.x) >> 5;  // one warp / node
    int lane = threadIdx.x & 31;
    if (gw >= NN) return;
    const int n = gw;

    const float2* __restrict__ m1v = (const float2*)g_m1;
    const float2* __restrict__ m2v = (const float2*)g_m2;

    float ax = 0.f, ay = 0.f;
    int b = g_off1[n], e = g_off1[n + 1];
    for (int j = b; j < e; j++) {
        int s = g_nbr1[j];                    // warp-uniform -> broadcast
        float2 v = m1v[s * 32 + lane];
        ax += v.x; ay += v.y;
    }
    float inv1 = 1.0f / (float)max(e - b, 1);

    float cx = 0.f, cy = 0.f;
    b = g_off2[n]; e = g_off2[n + 1];
    for (int j = b; j < e; j++) {
        int d = g_nbr2[j];
        float2 v = m2v[d * 32 + lane];
        cx += v.x; cy += v.y;
    }
    float inv2 = 1.0f / (float)max(e - b, 1);

    const float2* __restrict__ rv = (const float2*)g_r;
    float2 r = rv[n * 32 + lane];
    float h0 = fmaxf(r.x + ax * inv1 + cx * inv2, 0.f);
    float h1 = fmaxf(r.y + ay * inv1 + cy * inv2, 0.f);

    float2* hv = (float2*)g_h;
    hv[n * 32 + lane] = make_float2(h0, h1);
    float2* cv = (float2*)g_cat;
    cv[(n * DCAT + (l + 1) * D) / 2 + lane] = make_float2(h0, h1);
}

// ---------------- final: out = cat @ final_w^T + final_b --------------------
__global__ void k_final(const float* __restrict__ fw, const float* __restrict__ fb,
                        float* __restrict__ out) {
    __shared__ float sw[128 * D];            // 32 KB, two K-chunks of 128
    const int tid = threadIdx.x;
    int gid = blockIdx.x * 256 + tid;        // grid sized exactly NN*D
    int n = gid >> 6, c = gid & 63;
    float acc = fb[c];
    const float* __restrict__ crow = g_cat + n * DCAT;

    for (int ch = 0; ch < 2; ch++) {
        __syncthreads();
        for (int i = tid; i < 128 * D; i += 256) {
            int kk = i >> 6, c2 = i & 63;
            sw[kk * D + c2] = fw[c2 * DCAT + ch * 128 + kk];
        }
        __syncthreads();
#pragma unroll 8
        for (int kk = 0; kk < 128; kk++) {
            acc = fmaf(crow[ch * 128 + kk], sw[kk * D + c], acc);
        }
    }
    out[gid] = acc;
}

// ---------------- launch -----------------------------------------------------
extern "C" void kernel_launch(void* const* d_in, const int* in_sizes, int n_in,
                              void* d_out, int out_size) {
    const float* x     = (const float*)d_in[0];
    const int*   ei    = (const int*)d_in[1];
    const float* lin1  = (const float*)d_in[2];
    const float* lin2  = (const float*)d_in[3];
    const float* rootw = (const float*)d_in[4];
    const float* rootb = (const float*)d_in[5];
    const float* fw    = (const float*)d_in[6];
    const float* fb    = (const float*)d_in[7];
    float*       out   = (float*)d_out;

    k_init <<<(NN * D + 255) / 256, 256>>>(x);
    k_count<<<(NE + 255) / 256, 256>>>(ei);
    k_scan <<<1, 1024>>>();
    k_fill <<<(NE + 255) / 256, 256>>>(ei);

    for (int l = 0; l < NL; l++) {
        k_proj<<<NN * D / 256, 256>>>(lin1 + l * D * D, lin2 + l * D * D,
                                      rootw + l * D * D, rootb + l * D);
        k_agg <<<(NN * 32 + 255) / 256, 256>>>(l);
    }
    k_final<<<NN * D / 256, 256>>>(fw, fb, out);
}

// round 4
// speedup vs baseline: 3.5260x; 3.5260x over previous
#include <cuda_runtime.h>

#define NN 50000
#define NE 800000
#define D  64
#define NL 3
#define DCAT (D + NL * D)   // 256

// ---------------- scratch (device globals) ----------------------------------
__device__ int   g_cnt1[NN], g_cnt2[NN], g_cur1[NN], g_cur2[NN];
__device__ int   g_off1[NN + 1], g_off2[NN + 1];
__device__ int   g_nbr1[NE], g_nbr2[NE];
__device__ __align__(16) float g_h[NN * D];
__device__ __align__(16) float g_s1[NN * D];
__device__ __align__(16) float g_s2[NN * D];
__device__ __align__(16) float g_cat[NN * DCAT];

__device__ __forceinline__ int clampi(int v) {
    return v < 0 ? 0 : (v >= NN ? NN - 1 : v);
}

// ---------------- init: h = x, cat[:, :64] = x, zero CSR counters -----------
__global__ void k_init(const float* __restrict__ x) {
    int i = blockIdx.x * blockDim.x + threadIdx.x;
    if (i < NN * D) {
        float v = x[i];
        g_h[i] = v;
        g_cat[(i >> 6) * DCAT + (i & 63)] = v;
    }
    if (i < NN) {
        g_cnt1[i] = 0; g_cnt2[i] = 0;
        g_cur1[i] = 0; g_cur2[i] = 0;
    }
}

// ---------------- CSR build: histogram (edge_index is int32) ----------------
__global__ void k_count(const int* __restrict__ ei) {
    int e = blockIdx.x * blockDim.x + threadIdx.x;
    if (e >= NE) return;
    int s = clampi(ei[e]);
    int d = clampi(ei[NE + e]);
    atomicAdd(&g_cnt1[d], 1);   // CSR1: grouped by dst, stores src
    atomicAdd(&g_cnt2[s], 1);   // CSR2: grouped by src, stores dst
}

// ---------------- CSR build: single-block exclusive scan --------------------
__global__ void k_scan() {
    __shared__ int ssum1[1024], ssum2[1024];
    const int t  = threadIdx.x;
    const int CH = (NN + 1023) / 1024;  // 49
    const int base = t * CH;

    int s1 = 0, s2 = 0;
    for (int i = 0; i < CH; i++) {
        int n = base + i;
        if (n < NN) { s1 += g_cnt1[n]; s2 += g_cnt2[n]; }
    }
    ssum1[t] = s1; ssum2[t] = s2;
    __syncthreads();

    for (int off = 1; off < 1024; off <<= 1) {
        int a1 = ssum1[t], a2 = ssum2[t];
        int b1 = (t >= off) ? ssum1[t - off] : 0;
        int b2 = (t >= off) ? ssum2[t - off] : 0;
        __syncthreads();
        ssum1[t] = a1 + b1; ssum2[t] = a2 + b2;
        __syncthreads();
    }

    int ex1 = (t == 0) ? 0 : ssum1[t - 1];
    int ex2 = (t == 0) ? 0 : ssum2[t - 1];
    for (int i = 0; i < CH; i++) {
        int n = base + i;
        if (n < NN) {
            g_off1[n] = ex1; ex1 += g_cnt1[n];
            g_off2[n] = ex2; ex2 += g_cnt2[n];
        }
    }
    if (t == 0) {
        g_off1[NN] = ssum1[1023];
        g_off2[NN] = ssum2[1023];
    }
}

// ---------------- CSR build: fill edge lists --------------------------------
__global__ void k_fill(const int* __restrict__ ei) {
    int e = blockIdx.x * blockDim.x + threadIdx.x;
    if (e >= NE) return;
    int s = clampi(ei[e]);
    int d = clampi(ei[NE + e]);
    g_nbr1[g_off1[d] + atomicAdd(&g_cur1[d], 1)] = s;
    g_nbr2[g_off2[s] + atomicAdd(&g_cur2[s], 1)] = d;
}

// ---------------- high-MLP directed gather-mean of h ------------------------
__device__ __forceinline__ void gather_dir(const int* __restrict__ nbr,
                                           const float2* __restrict__ hv,
                                           int b, int e, int lane,
                                           float& ox, float& oy) {
    float ax = 0.f, ay = 0.f, bx = 0.f, by = 0.f;
    for (int j0 = b; j0 < e; j0 += 32) {
        int m = e - j0; if (m > 32) m = 32;
        // one coalesced index load covers up to 32 neighbors
        int idx = nbr[j0 + (lane < m ? lane : 0)];
        int jj = 0;
        for (; jj + 4 <= m; jj += 4) {
            int i0 = __shfl_sync(0xffffffffu, idx, jj);
            int i1 = __shfl_sync(0xffffffffu, idx, jj + 1);
            int i2 = __shfl_sync(0xffffffffu, idx, jj + 2);
            int i3 = __shfl_sync(0xffffffffu, idx, jj + 3);
            float2 v0 = hv[i0 * 32 + lane];
            float2 v1 = hv[i1 * 32 + lane];
            float2 v2 = hv[i2 * 32 + lane];
            float2 v3 = hv[i3 * 32 + lane];
            ax += v0.x + v1.x; ay += v0.y + v1.y;
            bx += v2.x + v3.x; by += v2.y + v3.y;
        }
        for (; jj < m; jj++) {
            int i0 = __shfl_sync(0xffffffffu, idx, jj);
            float2 v0 = hv[i0 * 32 + lane];
            ax += v0.x; ay += v0.y;
        }
    }
    ox = ax + bx; oy = ay + by;
}

// s1[n] = mean_{src -> n} h[src],  s2[n] = mean_{n -> dst} h[dst]
__global__ void k_agg() {
    int gw   = (blockIdx.x * blockDim.x + threadIdx.x) >> 5;
    int lane = threadIdx.x & 31;
    if (gw >= NN) return;
    const int n = gw;
    const float2* __restrict__ hv = (const float2*)g_h;

    int b1 = g_off1[n], e1 = g_off1[n + 1];
    float ax, ay;
    gather_dir(g_nbr1, hv, b1, e1, lane, ax, ay);
    float inv1 = 1.0f / (float)max(e1 - b1, 1);

    int b2 = g_off2[n], e2 = g_off2[n + 1];
    float cx, cy;
    gather_dir(g_nbr2, hv, b2, e2, lane, cx, cy);
    float inv2 = 1.0f / (float)max(e2 - b2, 1);

    ((float2*)g_s1)[n * 32 + lane] = make_float2(ax * inv1, ay * inv1);
    ((float2*)g_s2)[n * 32 + lane] = make_float2(cx * inv2, cy * inv2);
}

// ---------------- fused layer GEMM: h = relu([h,s1,s2] @ [Wr;W1;W2]^T + b) --
#define LT 25                    // tiles (of 4 nodes) per block
#define LAYER_SMEM ((64 * 49 + 4 * 48) * (int)sizeof(float4))   // 53248 B
__global__ void k_layer(const float* __restrict__ w1, const float* __restrict__ w2,
                        const float* __restrict__ wr, const float* __restrict__ rb,
                        int l) {
    extern __shared__ float4 dsm[];
    float4* sw4 = dsm;                   // [c][kq], padded stride 49
    float4* sx4 = dsm + 64 * 49;         // [n_local][kq]
    const int tid = threadIdx.x;

    // weights, native [c][k] layout; k-order: 0-15 Wr, 16-31 W1, 32-47 W2 (float4 units)
    for (int i4 = tid; i4 < 64 * 48; i4 += 256) {
        int c = i4 / 48, kq = i4 % 48;
        int src = kq >> 4, kk4 = kq & 15;
        const float* w = (src == 0) ? wr : (src == 1) ? w1 : w2;
        sw4[c * 49 + kq] = ((const float4*)w)[c * 16 + kk4];
    }

    const int n_local = tid >> 6;        // 0..3
    const int c       = tid & 63;
    const float bias  = rb[c];

    for (int t = 0; t < LT; t++) {
        int node0 = (blockIdx.x * LT + t) * 4;
        __syncthreads();
        for (int i4 = tid; i4 < 4 * 48; i4 += 256) {
            int nl = i4 / 48, kq = i4 % 48;
            int src = kq >> 4, kk4 = kq & 15;
            int node = node0 + nl;
            const float* xp = (src == 0) ? (g_h + node * D)
                            : (src == 1) ? (g_s1 + node * D)
                                         : (g_s2 + node * D);
            sx4[nl * 48 + kq] = ((const float4*)xp)[kk4];
        }
        __syncthreads();

        float acc = bias;
#pragma unroll
        for (int kq = 0; kq < 48; kq++) {
            float4 wv = sw4[c * 49 + kq];
            float4 xv = sx4[n_local * 48 + kq];
            acc = fmaf(xv.x, wv.x, acc);
            acc = fmaf(xv.y, wv.y, acc);
            acc = fmaf(xv.z, wv.z, acc);
            acc = fmaf(xv.w, wv.w, acc);
        }
        float h = fmaxf(acc, 0.f);
        int node = node0 + n_local;
        g_h[node * D + c] = h;
        g_cat[node * DCAT + (l + 1) * D + c] = h;
    }
}

// ---------------- final: out = cat @ final_w^T + final_b --------------------
#define FINAL_SMEM ((64 * 65 + 4 * 64) * (int)sizeof(float4))   // 70656 B
__global__ void k_final(const float* __restrict__ fw, const float* __restrict__ fb,
                        float* __restrict__ out) {
    extern __shared__ float4 dsm[];
    float4* sw4 = dsm;                   // [c][kq], padded stride 65
    float4* sx4 = dsm + 64 * 65;
    const int tid = threadIdx.x;

    for (int i4 = tid; i4 < 64 * 64; i4 += 256) {
        int c = i4 >> 6, kq = i4 & 63;
        sw4[c * 65 + kq] = ((const float4*)fw)[c * 64 + kq];
    }

    const int n_local = tid >> 6;
    const int c       = tid & 63;
    const float bias  = fb[c];

    for (int t = 0; t < LT; t++) {
        int node0 = (blockIdx.x * LT + t) * 4;
        __syncthreads();
        for (int i4 = tid; i4 < 4 * 64; i4 += 256) {
            int nl = i4 >> 6, kq = i4 & 63;
            sx4[i4] = ((const float4*)(g_cat + (node0 + nl) * DCAT))[kq];
        }
        __syncthreads();

        float acc = bias;
#pragma unroll
        for (int kq = 0; kq < 64; kq++) {
            float4 wv = sw4[c * 65 + kq];
            float4 xv = sx4[n_local * 64 + kq];
            acc = fmaf(xv.x, wv.x, acc);
            acc = fmaf(xv.y, wv.y, acc);
            acc = fmaf(xv.z, wv.z, acc);
            acc = fmaf(xv.w, wv.w, acc);
        }
        out[(node0 + n_local) * D + c] = acc;
    }
}

// ---------------- launch -----------------------------------------------------
extern "C" void kernel_launch(void* const* d_in, const int* in_sizes, int n_in,
                              void* d_out, int out_size) {
    const float* x     = (const float*)d_in[0];
    const int*   ei    = (const int*)d_in[1];
    const float* lin1  = (const float*)d_in[2];
    const float* lin2  = (const float*)d_in[3];
    const float* rootw = (const float*)d_in[4];
    const float* rootb = (const float*)d_in[5];
    const float* fw    = (const float*)d_in[6];
    const float* fb    = (const float*)d_in[7];
    float*       out   = (float*)d_out;

    // raise dynamic-smem caps (host-side, non-allocating, capture-safe)
    cudaFuncSetAttribute(k_layer, cudaFuncAttributeMaxDynamicSharedMemorySize, LAYER_SMEM);
    cudaFuncSetAttribute(k_final, cudaFuncAttributeMaxDynamicSharedMemorySize, FINAL_SMEM);

    k_init <<<(NN * D + 255) / 256, 256>>>(x);
    k_count<<<(NE + 255) / 256, 256>>>(ei);
    k_scan <<<1, 1024>>>();
    k_fill <<<(NE + 255) / 256, 256>>>(ei);

    const int agg_grid  = (NN * 32 + 255) / 256;
    const int gemm_grid = NN / (4 * LT);          // 500

    for (int l = 0; l < NL; l++) {
        k_agg  <<<agg_grid, 256>>>();
        k_layer<<<gemm_grid, 256, LAYER_SMEM>>>(lin1 + l * D * D, lin2 + l * D * D,
                                                rootw + l * D * D, rootb + l * D, l);
    }
    k_final<<<gemm_grid, 256, FINAL_SMEM>>>(fw, fb, out);
}